// round 1
// baseline (speedup 1.0000x reference)
#include <cuda_runtime.h>

#define B_   64
#define A_   1024
#define D_   5
#define F_   256
#define NB_  6
#define O_   256
#define K_   262        // F_ + NB_
#define TM   32         // rows per CTA
#define KSTR 36         // feats_T row stride in floats (16B-aligned LDS128 for all k, bounded STS conflicts)
#define NTHR 256
#define WSTRIDE (K_ * O_)   // 67072 floats per degree matrix

typedef unsigned long long ull;

__device__ __forceinline__ ull pack2(float x) {
    ull r; asm("mov.b64 %0, {%1, %1};" : "=l"(r) : "f"(x)); return r;
}
__device__ __forceinline__ void fma2(ull& a, ull x, ull y) {
    asm("fma.rn.f32x2 %0, %1, %2, %0;" : "+l"(a) : "l"(x), "l"(y));
}

__global__ void __launch_bounds__(NTHR, 3)
nfp_kernel(const float* __restrict__ atoms,
           const float* __restrict__ bonds,
           const int*   __restrict__ edges,
           const float* __restrict__ degW,
           const float* __restrict__ bias,
           float*       __restrict__ out)
{
    __shared__ float    fT[K_ * KSTR];   // transposed feats: [k][row], stride 36
    __shared__ int      deg_s[TM];
    __shared__ int      edg_s[TM * D_];
    __shared__ unsigned pres_s;          // bitmask of degrees present in this tile

    const int tid = threadIdx.x;
    const int g0  = blockIdx.x * TM;     // global row base
    const int bi  = g0 >> 10;            // batch index (A_ = 1024)
    const int a0  = g0 & (A_ - 1);       // atom base within batch
    const float* atomsB = atoms + (size_t)bi * (A_ * F_);

    if (tid == 0) pres_s = 0u;
    __syncthreads();

    // ---- edges / degree / presence mask ----
    if (tid < TM) {
        const int* e = edges + (size_t)(bi * A_ + a0 + tid) * D_;
        int d = 0;
        #pragma unroll
        for (int j = 0; j < D_; j++) {
            int ej = e[j];
            edg_s[tid * D_ + j] = ej;
            d += (ej >= 0);
        }
        deg_s[tid] = d;
        atomicOr(&pres_s, 1u << d);
    }
    __syncthreads();

    // ---- phase 1: build feats (self + valid-neighbor gather), store transposed ----
    {
        const float4* atoms4 = (const float4*)atomsB;
        for (int t = tid; t < TM * (F_ / 4); t += NTHR) {
            int r = t >> 6;          // row 0..31 (64 float4-lanes per row)
            int c = t & 63;          // float4 column
            float4 v = atoms4[(size_t)(a0 + r) * (F_ / 4) + c];
            #pragma unroll
            for (int j = 0; j < D_; j++) {
                int e = edg_s[r * D_ + j];
                if (e >= 0) {
                    float4 n = atoms4[(size_t)e * (F_ / 4) + c];
                    v.x += n.x; v.y += n.y; v.z += n.z; v.w += n.w;
                }
            }
            fT[(4 * c + 0) * KSTR + r] = v.x;
            fT[(4 * c + 1) * KSTR + r] = v.y;
            fT[(4 * c + 2) * KSTR + r] = v.z;
            fT[(4 * c + 3) * KSTR + r] = v.w;
        }
        // bonds summed over D -> feature slots 256..261
        const float* bb = bonds + (size_t)(bi * A_ + a0) * (D_ * NB_);
        for (int t = tid; t < TM * NB_; t += NTHR) {
            int r  = t / NB_;
            int nb = t - r * NB_;
            float s = 0.f;
            #pragma unroll
            for (int j = 0; j < D_; j++) s += bb[r * (D_ * NB_) + j * NB_ + nb];
            fT[(F_ + nb) * KSTR + r] = s;
        }
    }
    __syncthreads();

    // ---- phase 2: per present degree, GEMV with packed f32x2 FMA ----
    const int o = tid;                    // output column, coalesced across warp
    const float bo = bias[o];
    const unsigned pres = pres_s;
    float* outB = out + (size_t)g0 * O_ + o;

    for (int d = 0; d < 6; d++) {
        if (!((pres >> d) & 1u)) continue;       // uniform branch (all threads share tile)
        const float* Wo = degW + (size_t)d * WSTRIDE + o;

        ull acc[TM / 2];
        #pragma unroll
        for (int q = 0; q < TM / 2; q++) acc[q] = 0ull;

        float w = Wo[0];
        for (int k = 0; k < K_; k++) {
            float wn = (k + 1 < K_) ? Wo[(size_t)(k + 1) << 8] : 0.f;   // prefetch next weight
            ull w2 = pack2(w);
            const float* f = fT + k * KSTR;
            #pragma unroll
            for (int q4 = 0; q4 < TM / 4; q4++) {
                ulonglong2 fv = *(const ulonglong2*)(f + 4 * q4);  // rows 4q4..4q4+3 as two f32x2
                fma2(acc[2 * q4 + 0], fv.x, w2);
                fma2(acc[2 * q4 + 1], fv.y, w2);
            }
            w = wn;
        }

        // epilogue: bias + sigmoid, write only rows whose degree == d
        #pragma unroll
        for (int q = 0; q < TM / 2; q++) {
            float x0, x1;
            asm("mov.b64 {%0, %1}, %2;" : "=f"(x0), "=f"(x1) : "l"(acc[q]));
            int r0 = 2 * q, r1 = 2 * q + 1;
            if (deg_s[r0] == d) {
                float z = x0 + bo;
                outB[(size_t)r0 * O_] = __fdividef(1.f, 1.f + __expf(-z));
            }
            if (deg_s[r1] == d) {
                float z = x1 + bo;
                outB[(size_t)r1 * O_] = __fdividef(1.f, 1.f + __expf(-z));
            }
        }
    }
}

extern "C" void kernel_launch(void* const* d_in, const int* in_sizes, int n_in,
                              void* d_out, int out_size) {
    const float* atoms = (const float*)d_in[0];
    const float* bonds = (const float*)d_in[1];
    const int*   edges = (const int*)d_in[2];
    const float* degW  = (const float*)d_in[3];
    const float* bvec  = (const float*)d_in[4];
    float* out = (float*)d_out;

    const int nblocks = (B_ * A_) / TM;   // 2048
    nfp_kernel<<<nblocks, NTHR>>>(atoms, bonds, edges, degW, bvec, out);
}

// round 2
// speedup vs baseline: 1.6156x; 1.6156x over previous
#include <cuda_runtime.h>

#define B_   64
#define A_   1024
#define D_   5
#define F_   256
#define NB_  6
#define O_   256
#define K_   262        // F_ + NB_
#define TM   32         // rows per CTA
#define KSTR 36         // feats_T row stride in floats (16B-aligned LDS128 for all k)
#define NTHR 256
#define WSTRIDE (K_ * O_)   // 67072 floats per degree matrix

typedef unsigned long long ull;

__device__ __forceinline__ ull pack2(float x) {
    ull r; asm("mov.b64 %0, {%1, %1};" : "=l"(r) : "f"(x)); return r;
}
__device__ __forceinline__ void fma2(ull& a, ull x, ull y) {
    asm("fma.rn.f32x2 %0, %1, %2, %0;" : "+l"(a) : "l"(x), "l"(y));
}
__device__ __forceinline__ float sigmoidf_fast(float z) {
    return __fdividef(1.f, 1.f + __expf(-z));
}

__global__ void __launch_bounds__(NTHR, 3)
nfp_kernel(const float* __restrict__ atoms,
           const float* __restrict__ bonds,
           const int*   __restrict__ edges,
           const float* __restrict__ degW,
           const float* __restrict__ bias,
           float*       __restrict__ out)
{
    __shared__ __align__(16) float fT[K_ * KSTR];   // transposed feats: [k][row]
    __shared__ int      deg_s[TM];
    __shared__ int      edg_s[TM * D_];
    __shared__ unsigned pres_s;

    const int tid = threadIdx.x;
    const int g0  = blockIdx.x * TM;
    const int bi  = g0 >> 10;            // batch index (A_ = 1024)
    const int a0  = g0 & (A_ - 1);
    const float* atomsB = atoms + (size_t)bi * (A_ * F_);

    if (tid == 0) pres_s = 0u;
    __syncthreads();

    // ---- edges / degree / presence mask ----
    if (tid < TM) {
        const int* e = edges + (size_t)(bi * A_ + a0 + tid) * D_;
        int d = 0;
        #pragma unroll
        for (int j = 0; j < D_; j++) {
            int ej = e[j];
            edg_s[tid * D_ + j] = ej;
            d += (ej >= 0);
        }
        deg_s[tid] = d;
        atomicOr(&pres_s, 1u << d);
    }
    __syncthreads();

    // ---- phase 1: self + valid-neighbor gather, stored transposed ----
    {
        const float4* atoms4 = (const float4*)atomsB;
        for (int t = tid; t < TM * (F_ / 4); t += NTHR) {
            int r = t >> 6;          // row 0..31
            int c = t & 63;          // float4 column
            float4 v = atoms4[(size_t)(a0 + r) * (F_ / 4) + c];
            #pragma unroll
            for (int j = 0; j < D_; j++) {
                int e = edg_s[r * D_ + j];
                if (e >= 0) {
                    float4 n = atoms4[(size_t)e * (F_ / 4) + c];
                    v.x += n.x; v.y += n.y; v.z += n.z; v.w += n.w;
                }
            }
            fT[(4 * c + 0) * KSTR + r] = v.x;
            fT[(4 * c + 1) * KSTR + r] = v.y;
            fT[(4 * c + 2) * KSTR + r] = v.z;
            fT[(4 * c + 3) * KSTR + r] = v.w;
        }
        const float* bb = bonds + (size_t)(bi * A_ + a0) * (D_ * NB_);
        for (int t = tid; t < TM * NB_; t += NTHR) {
            int r  = t / NB_;
            int nb = t - r * NB_;
            float s = 0.f;
            #pragma unroll
            for (int j = 0; j < D_; j++) s += bb[r * (D_ * NB_) + j * NB_ + nb];
            fT[(F_ + nb) * KSTR + r] = s;
        }
    }
    __syncthreads();

    // ---- phase 2: thread = (col-pair, row-half); 16 rows x 2 cols per thread ----
    const int c2 = tid & 127;            // cols 2*c2, 2*c2+1
    const int h  = tid >> 7;             // row half: rows 16h .. 16h+15
    const float2 bo = ((const float2*)bias)[c2];
    const unsigned pres = pres_s;
    const float* fbase = fT + 16 * h;
    float* outB = out + (size_t)(g0 + 16 * h) * O_ + 2 * c2;

    for (int d = 0; d < 6; d++) {
        if (!((pres >> d) & 1u)) continue;           // uniform branch

        const float* wp = degW + (size_t)d * WSTRIDE + 2 * c2;

        ull acc[16];
        #pragma unroll
        for (int q = 0; q < 16; q++) acc[q] = 0ull;

        float2 w = *(const float2*)wp;               // weights for k=0
        const float* f = fbase;

        #pragma unroll 2
        for (int k = 0; k < K_ - 1; k++) {
            float2 wn = *(const float2*)(wp + (size_t)(k + 1) * O_);  // prefetch
            ull w0 = pack2(w.x);
            ull w1 = pack2(w.y);
            ulonglong2 fa = *(const ulonglong2*)(f + 0);   // rows +0..3
            ulonglong2 fb = *(const ulonglong2*)(f + 4);   // rows +4..7
            ulonglong2 fc = *(const ulonglong2*)(f + 8);   // rows +8..11
            ulonglong2 fd = *(const ulonglong2*)(f + 12);  // rows +12..15
            fma2(acc[0], fa.x, w0);  fma2(acc[8],  fa.x, w1);
            fma2(acc[1], fa.y, w0);  fma2(acc[9],  fa.y, w1);
            fma2(acc[2], fb.x, w0);  fma2(acc[10], fb.x, w1);
            fma2(acc[3], fb.y, w0);  fma2(acc[11], fb.y, w1);
            fma2(acc[4], fc.x, w0);  fma2(acc[12], fc.x, w1);
            fma2(acc[5], fc.y, w0);  fma2(acc[13], fc.y, w1);
            fma2(acc[6], fd.x, w0);  fma2(acc[14], fd.x, w1);
            fma2(acc[7], fd.y, w0);  fma2(acc[15], fd.y, w1);
            f += KSTR;
            w = wn;
        }
        {   // last k (no prefetch)
            ull w0 = pack2(w.x);
            ull w1 = pack2(w.y);
            ulonglong2 fa = *(const ulonglong2*)(f + 0);
            ulonglong2 fb = *(const ulonglong2*)(f + 4);
            ulonglong2 fc = *(const ulonglong2*)(f + 8);
            ulonglong2 fd = *(const ulonglong2*)(f + 12);
            fma2(acc[0], fa.x, w0);  fma2(acc[8],  fa.x, w1);
            fma2(acc[1], fa.y, w0);  fma2(acc[9],  fa.y, w1);
            fma2(acc[2], fb.x, w0);  fma2(acc[10], fb.x, w1);
            fma2(acc[3], fb.y, w0);  fma2(acc[11], fb.y, w1);
            fma2(acc[4], fc.x, w0);  fma2(acc[12], fc.x, w1);
            fma2(acc[5], fc.y, w0);  fma2(acc[13], fc.y, w1);
            fma2(acc[6], fd.x, w0);  fma2(acc[14], fd.x, w1);
            fma2(acc[7], fd.y, w0);  fma2(acc[15], fd.y, w1);
        }

        // epilogue: bias + sigmoid, float2 store per matching row
        #pragma unroll
        for (int q = 0; q < 8; q++) {
            float a0lo, a0hi, a1lo, a1hi;
            asm("mov.b64 {%0, %1}, %2;" : "=f"(a0lo), "=f"(a0hi) : "l"(acc[q]));
            asm("mov.b64 {%0, %1}, %2;" : "=f"(a1lo), "=f"(a1hi) : "l"(acc[8 + q]));
            int r0 = 16 * h + 2 * q;
            int r1 = r0 + 1;
            if (deg_s[r0] == d) {
                float2 v = make_float2(sigmoidf_fast(a0lo + bo.x),
                                       sigmoidf_fast(a1lo + bo.y));
                *(float2*)(outB + (size_t)(2 * q) * O_) = v;
            }
            if (deg_s[r1] == d) {
                float2 v = make_float2(sigmoidf_fast(a0hi + bo.x),
                                       sigmoidf_fast(a1hi + bo.y));
                *(float2*)(outB + (size_t)(2 * q + 1) * O_) = v;
            }
        }
    }
}

extern "C" void kernel_launch(void* const* d_in, const int* in_sizes, int n_in,
                              void* d_out, int out_size) {
    const float* atoms = (const float*)d_in[0];
    const float* bonds = (const float*)d_in[1];
    const int*   edges = (const int*)d_in[2];
    const float* degW  = (const float*)d_in[3];
    const float* bvec  = (const float*)d_in[4];
    float* out = (float*)d_out;

    const int nblocks = (B_ * A_) / TM;   // 2048
    nfp_kernel<<<nblocks, NTHR>>>(atoms, bonds, edges, degW, bvec, out);
}

// round 3
// speedup vs baseline: 1.8642x; 1.1539x over previous
#include <cuda_runtime.h>

#define B_   64
#define A_   1024
#define D_   5
#define F_   256
#define NB_  6
#define O_   256
#define K_   262
#define TM   64
#define NTHR 256
#define ROWS_TOTAL (B_ * A_)
#define WSTRIDE (K_ * O_)

typedef unsigned long long ull;

__device__ int g_cnt[8];
__device__ int g_lists[6][ROWS_TOTAL];

__device__ __forceinline__ ull pack2(float x) {
    ull r; asm("mov.b64 %0, {%1, %1};" : "=l"(r) : "f"(x)); return r;
}
__device__ __forceinline__ void fma2(ull& a, ull x, ull y) {
    asm("fma.rn.f32x2 %0, %1, %2, %0;" : "+l"(a) : "l"(x), "l"(y));
}
__device__ __forceinline__ float sigmoidf_fast(float z) {
    return __fdividef(1.f, 1.f + __expf(-z));
}

__global__ void zero_kernel() {
    if (threadIdx.x < 8) g_cnt[threadIdx.x] = 0;
}

__global__ void classify_kernel(const int* __restrict__ edges) {
    int rid = blockIdx.x * blockDim.x + threadIdx.x;
    const int* e = edges + (size_t)rid * D_;
    int d = 0;
    #pragma unroll
    for (int j = 0; j < D_; j++) d += (e[j] >= 0);
    unsigned lt = (1u << (threadIdx.x & 31)) - 1u;
    #pragma unroll
    for (int dd = 0; dd < 6; dd++) {
        unsigned m = __ballot_sync(0xffffffffu, d == dd);
        if (d == dd) {
            int leader = __ffs(m) - 1;
            int base = 0;
            if ((int)(threadIdx.x & 31) == leader) base = atomicAdd(&g_cnt[dd], __popc(m));
            base = __shfl_sync(m, base, leader);
            g_lists[dd][base + __popc(m & lt)] = rid;
        }
    }
}

extern __shared__ float fT[];   // [K_][64] floats, XOR-swizzled on 4-row groups

__global__ void __launch_bounds__(NTHR, 2)
nfp_gemm(const float* __restrict__ atoms,
         const float* __restrict__ bonds,
         const int*   __restrict__ edges,
         const float* __restrict__ degW,
         const float* __restrict__ bias,
         float*       __restrict__ out)
{
    __shared__ int rid_s[TM];
    __shared__ int deg_s[TM];
    __shared__ int edg_s[TM * D_];
    __shared__ unsigned pres_s;

    const int tid = threadIdx.x;
    if (tid == 0) pres_s = 0u;
    __syncthreads();

    // ---- map tile slots -> bucketed rows ----
    if (tid < TM) {
        int s = blockIdx.x * TM + tid;
        int accc = 0, d = 0, idx = 0;
        #pragma unroll
        for (int dd = 0; dd < 6; dd++) {
            int c = g_cnt[dd];
            if (s >= accc && s < accc + c) { d = dd; idx = s - accc; }
            accc += c;
        }
        int rid = g_lists[d][idx];
        rid_s[tid] = rid;
        deg_s[tid] = d;
        atomicOr(&pres_s, 1u << d);
        const int* e = edges + (size_t)rid * D_;
        #pragma unroll
        for (int j = 0; j < D_; j++) edg_s[tid * D_ + j] = e[j];
    }
    __syncthreads();

    // ---- phase 1: gather self+neighbors, store transposed (swizzled) ----
    {
        const float4* atoms4 = (const float4*)atoms;
        for (int t = tid; t < TM * (F_ / 4); t += NTHR) {
            int r = t >> 6;          // row 0..63
            int c = t & 63;          // float4 column; k = 4c+j, (k>>2) = c
            int rid = rid_s[r];
            int bbase = rid & ~(A_ - 1);
            float4 v = atoms4[(size_t)rid * (F_ / 4) + c];
            #pragma unroll
            for (int j = 0; j < D_; j++) {
                int e = edg_s[r * D_ + j];
                if (e >= 0) {
                    float4 n = atoms4[(size_t)(bbase + e) * (F_ / 4) + c];
                    v.x += n.x; v.y += n.y; v.z += n.z; v.w += n.w;
                }
            }
            int gp = (r >> 2) ^ (c & 15);
            float* p = fT + (4 * c) * 64 + 4 * gp + (r & 3);
            p[0 * 64] = v.x;
            p[1 * 64] = v.y;
            p[2 * 64] = v.z;
            p[3 * 64] = v.w;
        }
        for (int t = tid; t < TM * NB_; t += NTHR) {
            int r  = t / NB_;
            int nb = t - r * NB_;
            const float* bb = bonds + (size_t)rid_s[r] * (D_ * NB_);
            float s = 0.f;
            #pragma unroll
            for (int j = 0; j < D_; j++) s += bb[j * NB_ + nb];
            int k = F_ + nb;
            int gp = (r >> 2) ^ ((k >> 2) & 15);
            fT[k * 64 + 4 * gp + (r & 3)] = s;
        }
    }
    __syncthreads();

    // ---- phase 2: thread = (c4: 4 cols, h: 16-row group) ----
    const int c4 = tid & 63;             // cols 4*c4 .. 4*c4+3
    const int h  = tid >> 6;             // rows 16h .. 16h+15
    const float4 bo = ((const float4*)bias)[c4];
    const unsigned pres = pres_s;

    for (int d = 0; d < 6; d++) {
        if (!((pres >> d) & 1u)) continue;       // uniform branch

        const float* wp = degW + (size_t)d * WSTRIDE + 4 * c4;

        ull acc2[8][4];
        #pragma unroll
        for (int q = 0; q < 8; q++)
            #pragma unroll
            for (int c = 0; c < 4; c++) acc2[q][c] = 0ull;

        float4 w = *(const float4*)wp;

        for (int k = 0; k < K_; k++) {
            float4 wn = (k < K_ - 1) ? *(const float4*)(wp + (size_t)(k + 1) * O_) : w;
            ull w2x = pack2(w.x);
            ull w2y = pack2(w.y);
            ull w2z = pack2(w.z);
            ull w2w = pack2(w.w);
            const int sk = (k >> 2) & 15;
            const float* fk = fT + k * 64;
            #pragma unroll
            for (int g = 0; g < 4; g++) {
                int G = 4 * h + g;
                ulonglong2 fv = *(const ulonglong2*)(fk + 4 * (G ^ sk));
                fma2(acc2[2 * g + 0][0], fv.x, w2x);
                fma2(acc2[2 * g + 0][1], fv.x, w2y);
                fma2(acc2[2 * g + 0][2], fv.x, w2z);
                fma2(acc2[2 * g + 0][3], fv.x, w2w);
                fma2(acc2[2 * g + 1][0], fv.y, w2x);
                fma2(acc2[2 * g + 1][1], fv.y, w2y);
                fma2(acc2[2 * g + 1][2], fv.y, w2z);
                fma2(acc2[2 * g + 1][3], fv.y, w2w);
            }
            w = wn;
        }

        // epilogue: q covers rows r0 = 16h + 4*(q>>1) + 2*(q&1), r0+1
        #pragma unroll
        for (int q = 0; q < 8; q++) {
            int r0 = 16 * h + 4 * (q >> 1) + 2 * (q & 1);
            int r1 = r0 + 1;
            float lo[4], hi[4];
            #pragma unroll
            for (int c = 0; c < 4; c++) {
                asm("mov.b64 {%0, %1}, %2;" : "=f"(lo[c]), "=f"(hi[c]) : "l"(acc2[q][c]));
            }
            if (deg_s[r0] == d) {
                float4 v = make_float4(sigmoidf_fast(lo[0] + bo.x),
                                       sigmoidf_fast(lo[1] + bo.y),
                                       sigmoidf_fast(lo[2] + bo.z),
                                       sigmoidf_fast(lo[3] + bo.w));
                *(float4*)(out + (size_t)rid_s[r0] * O_ + 4 * c4) = v;
            }
            if (deg_s[r1] == d) {
                float4 v = make_float4(sigmoidf_fast(hi[0] + bo.x),
                                       sigmoidf_fast(hi[1] + bo.y),
                                       sigmoidf_fast(hi[2] + bo.z),
                                       sigmoidf_fast(hi[3] + bo.w));
                *(float4*)(out + (size_t)rid_s[r1] * O_ + 4 * c4) = v;
            }
        }
    }
}

extern "C" void kernel_launch(void* const* d_in, const int* in_sizes, int n_in,
                              void* d_out, int out_size) {
    const float* atoms = (const float*)d_in[0];
    const float* bonds = (const float*)d_in[1];
    const int*   edges = (const int*)d_in[2];
    const float* degW  = (const float*)d_in[3];
    const float* bvec  = (const float*)d_in[4];
    float* out = (float*)d_out;

    const int smem = K_ * 64 * sizeof(float);   // 67584 B
    static int attr_set = 0;
    // idempotent attribute set (host-side, not a stream op; safe under capture)
    cudaFuncSetAttribute(nfp_gemm, cudaFuncAttributeMaxDynamicSharedMemorySize, smem);
    (void)attr_set;

    zero_kernel<<<1, 32>>>();
    classify_kernel<<<ROWS_TOTAL / 256, 256>>>(edges);
    nfp_gemm<<<ROWS_TOTAL / TM, NTHR, smem>>>(atoms, bonds, edges, degW, bvec, out);
}

// round 5
// speedup vs baseline: 2.2298x; 1.1961x over previous
#include <cuda_runtime.h>
#include <cstdint>

#define B_   64
#define A_   1024
#define D_   5
#define F_   256
#define NB_  6
#define O_   256
#define K_   262
#define TM   64
#define NTHR 256
#define CHK  32
#define NC   9            // 8 chunks of 32 + 1 bonds chunk of 6
#define ROWS_TOTAL (B_ * A_)
#define WSTRIDE (K_ * O_)

typedef unsigned long long ull;

__device__ int g_cnt[8];
__device__ int g_lists[6][ROWS_TOTAL];

__device__ __forceinline__ ull pack2(float x) {
    ull r; asm("mov.b64 %0, {%1, %1};" : "=l"(r) : "f"(x)); return r;
}
__device__ __forceinline__ void fma2(ull& a, ull x, ull y) {
    asm("fma.rn.f32x2 %0, %1, %2, %0;" : "+l"(a) : "l"(x), "l"(y));
}
__device__ __forceinline__ float sigf(float z) {
    return __fdividef(1.f, 1.f + __expf(-z));
}

__global__ void zero_kernel() {
    if (threadIdx.x < 8) g_cnt[threadIdx.x] = 0;
}

__global__ void classify_kernel(const int* __restrict__ edges) {
    int rid = blockIdx.x * blockDim.x + threadIdx.x;
    const int* e = edges + (size_t)rid * D_;
    int d = 0;
    #pragma unroll
    for (int j = 0; j < D_; j++) d += (e[j] >= 0);
    unsigned lt = (1u << (threadIdx.x & 31)) - 1u;
    #pragma unroll
    for (int dd = 0; dd < 6; dd++) {
        unsigned m = __ballot_sync(0xffffffffu, d == dd);
        if (d == dd) {
            int leader = __ffs(m) - 1;
            int base = 0;
            if ((int)(threadIdx.x & 31) == leader) base = atomicAdd(&g_cnt[dd], __popc(m));
            base = __shfl_sync(m, base, leader);
            g_lists[dd][base + __popc(m & lt)] = rid;
        }
    }
}

// ---- build one 32-k chunk of the transposed feats tile (swizzled) ----
__device__ __forceinline__ void build_chunk(float* __restrict__ dst, int c,
                                            const float* __restrict__ atoms,
                                            const float* __restrict__ bonds,
                                            const int* __restrict__ rid_s,
                                            const int* __restrict__ edg_s) {
    const int tid = threadIdx.x;
    if (c < 8) {
        const float4* a4 = (const float4*)atoms;
        #pragma unroll
        for (int it = 0; it < 2; it++) {
            int job = it * NTHR + tid;
            int r = job >> 3, c4 = job & 7;     // r 0..63, c4 0..7 (k' = 4c4..4c4+3)
            int rid = rid_s[r];
            int cg = c * 8 + c4;
            float4 v = a4[(size_t)rid * 64 + cg];
            int bbase = rid & ~(A_ - 1);
            #pragma unroll
            for (int j = 0; j < D_; j++) {
                int e = edg_s[r * D_ + j];
                if (e >= 0) {
                    float4 n = a4[(size_t)(bbase + e) * 64 + cg];
                    v.x += n.x; v.y += n.y; v.z += n.z; v.w += n.w;
                }
            }
            int p = (r >> 2) ^ c4;               // sk = k'>>2 = c4
            int base = (4 * c4) * 64 + 4 * p + (r & 3);
            dst[base + 0 * 64] = v.x;
            dst[base + 1 * 64] = v.y;
            dst[base + 2 * 64] = v.z;
            dst[base + 3 * 64] = v.w;
        }
    } else {
        // bonds chunk: k' = nb in [0, 6)
        #pragma unroll
        for (int it = 0; it < 2; it++) {
            int job = it * NTHR + tid;
            int r = job >> 3, c4 = job & 7;
            if (c4 < 2) {
                const float* bb = bonds + (size_t)rid_s[r] * (D_ * NB_);
                #pragma unroll
                for (int q = 0; q < 4; q++) {
                    int nb = 4 * c4 + q;
                    if (nb < NB_) {
                        float s = 0.f;
                        #pragma unroll
                        for (int j = 0; j < D_; j++) s += bb[j * NB_ + nb];
                        int p = (r >> 2) ^ (nb >> 2);
                        dst[nb * 64 + 4 * p + (r & 3)] = s;
                    }
                }
            }
        }
    }
}

// ---- GEMV over one chunk: 16 rows x 4 cols per thread ----
template <int NK>
__device__ __forceinline__ void gemv_chunk(const float* __restrict__ fb,
                                           const float* __restrict__ wk,  // + chunk_k*O_ + 4*c4col
                                           int h, ull acc[8][4]) {
    #pragma unroll
    for (int k4 = 0; k4 < (NK + 3) / 4; k4++) {
        const int sk = k4;
        int of0 = 4 * ((4 * h + 0) ^ sk);
        int of1 = 4 * ((4 * h + 1) ^ sk);
        int of2 = 4 * ((4 * h + 2) ^ sk);
        int of3 = 4 * ((4 * h + 3) ^ sk);
        const float* f0 = fb + k4 * 4 * 64;
        const int jmax = (NK - 4 * k4 < 4) ? (NK - 4 * k4) : 4;
        #pragma unroll
        for (int j = 0; j < jmax; j++) {
            float4 w = *(const float4*)(wk + (size_t)(4 * k4 + j) * O_);
            ull wx = pack2(w.x), wy = pack2(w.y), wz = pack2(w.z), ww = pack2(w.w);
            const float* fj = f0 + j * 64;
            ulonglong2 fa = *(const ulonglong2*)(fj + of0);
            ulonglong2 fb2 = *(const ulonglong2*)(fj + of1);
            ulonglong2 fc = *(const ulonglong2*)(fj + of2);
            ulonglong2 fd = *(const ulonglong2*)(fj + of3);
            fma2(acc[0][0], fa.x, wx); fma2(acc[0][1], fa.x, wy); fma2(acc[0][2], fa.x, wz); fma2(acc[0][3], fa.x, ww);
            fma2(acc[1][0], fa.y, wx); fma2(acc[1][1], fa.y, wy); fma2(acc[1][2], fa.y, wz); fma2(acc[1][3], fa.y, ww);
            fma2(acc[2][0], fb2.x, wx); fma2(acc[2][1], fb2.x, wy); fma2(acc[2][2], fb2.x, wz); fma2(acc[2][3], fb2.x, ww);
            fma2(acc[3][0], fb2.y, wx); fma2(acc[3][1], fb2.y, wy); fma2(acc[3][2], fb2.y, wz); fma2(acc[3][3], fb2.y, ww);
            fma2(acc[4][0], fc.x, wx); fma2(acc[4][1], fc.x, wy); fma2(acc[4][2], fc.x, wz); fma2(acc[4][3], fc.x, ww);
            fma2(acc[5][0], fc.y, wx); fma2(acc[5][1], fc.y, wy); fma2(acc[5][2], fc.y, wz); fma2(acc[5][3], fc.y, ww);
            fma2(acc[6][0], fd.x, wx); fma2(acc[6][1], fd.x, wy); fma2(acc[6][2], fd.x, wz); fma2(acc[6][3], fd.x, ww);
            fma2(acc[7][0], fd.y, wx); fma2(acc[7][1], fd.y, wy); fma2(acc[7][2], fd.y, wz); fma2(acc[7][3], fd.y, ww);
        }
    }
}

__global__ void __launch_bounds__(NTHR, 2)
nfp_gemm(const float* __restrict__ atoms,
         const float* __restrict__ bonds,
         const int*   __restrict__ edges,
         const float* __restrict__ degW,
         const float* __restrict__ bias,
         float*       __restrict__ out)
{
    __shared__ __align__(16) float fbuf[2][CHK * 64];   // 2 x 8KB
    __shared__ int      rid_s[TM];
    __shared__ int      deg_s[TM];
    __shared__ int      edg_s[TM * D_];
    __shared__ unsigned pres_s;

    const int tid = threadIdx.x;
    if (tid == 0) pres_s = 0u;
    __syncthreads();

    if (tid < TM) {
        int s = blockIdx.x * TM + tid;
        int accc = 0, d = 0, idx = 0;
        #pragma unroll
        for (int dd = 0; dd < 6; dd++) {
            int c = g_cnt[dd];
            if (s >= accc && s < accc + c) { d = dd; idx = s - accc; }
            accc += c;
        }
        int rid = g_lists[d][idx];
        rid_s[tid] = rid;
        deg_s[tid] = d;
        atomicOr(&pres_s, 1u << d);
        const int* e = edges + (size_t)rid * D_;
        #pragma unroll
        for (int j = 0; j < D_; j++) edg_s[tid * D_ + j] = e[j];
    }
    __syncthreads();

    const int c4 = tid & 63;            // cols 4*c4 .. 4*c4+3
    const int h  = tid >> 6;            // rows 16h .. 16h+15
    const float4 bo = ((const float4*)bias)[c4];
    const unsigned pres = pres_s;

    for (int d = 0; d < 6; d++) {
        if (!((pres >> d) & 1u)) continue;        // uniform branch

        const float* wbase = degW + (size_t)d * WSTRIDE + 4 * c4;

        ull acc[8][4];
        #pragma unroll
        for (int q = 0; q < 8; q++)
            #pragma unroll
            for (int cc = 0; cc < 4; cc++) acc[q][cc] = 0ull;

        build_chunk(fbuf[0], 0, atoms, bonds, rid_s, edg_s);
        __syncthreads();

        #pragma unroll 1
        for (int c = 0; c < NC; c++) {
            if (c + 1 < NC)
                build_chunk(fbuf[(c + 1) & 1], c + 1, atoms, bonds, rid_s, edg_s);
            const float* wk = wbase + (size_t)(c * CHK) * O_;
            if (c < 8) gemv_chunk<32>(fbuf[c & 1], wk, h, acc);
            else       gemv_chunk<6>(fbuf[c & 1], wk, h, acc);
            __syncthreads();
        }

        // epilogue: rows r0 = 16h + 4*(q>>1) + 2*(q&1), r0+1
        #pragma unroll
        for (int q = 0; q < 8; q++) {
            int r0 = 16 * h + 4 * (q >> 1) + 2 * (q & 1);
            int r1 = r0 + 1;
            float lo[4], hi[4];
            #pragma unroll
            for (int cc = 0; cc < 4; cc++) {
                asm("mov.b64 {%0, %1}, %2;" : "=f"(lo[cc]), "=f"(hi[cc]) : "l"(acc[q][cc]));
            }
            if (deg_s[r0] == d) {
                float4 v = make_float4(sigf(lo[0] + bo.x), sigf(lo[1] + bo.y),
                                       sigf(lo[2] + bo.z), sigf(lo[3] + bo.w));
                *(float4*)(out + (size_t)rid_s[r0] * O_ + 4 * c4) = v;
            }
            if (deg_s[r1] == d) {
                float4 v = make_float4(sigf(hi[0] + bo.x), sigf(hi[1] + bo.y),
                                       sigf(hi[2] + bo.z), sigf(hi[3] + bo.w));
                *(float4*)(out + (size_t)rid_s[r1] * O_ + 4 * c4) = v;
            }
        }
    }
}

extern "C" void kernel_launch(void* const* d_in, const int* in_sizes, int n_in,
                              void* d_out, int out_size) {
    const float* atoms = (const float*)d_in[0];
    const float* bonds = (const float*)d_in[1];
    const int*   edges = (const int*)d_in[2];
    const float* degW  = (const float*)d_in[3];
    const float* bvec  = (const float*)d_in[4];
    float* out = (float*)d_out;

    zero_kernel<<<1, 32>>>();
    classify_kernel<<<ROWS_TOTAL / 256, 256>>>(edges);
    nfp_gemm<<<ROWS_TOTAL / TM, NTHR>>>(atoms, bonds, edges, degW, bvec, out);
}